// round 17
// baseline (speedup 1.0000x reference)
#include <cuda_runtime.h>

#define NN 50000
#define EE 800000
#define DD 96
#define NV4 (NN * DD / 4)
#define NGB 148                        // persistent blocks (<= #SMs)
#define SCHUNK 512                     // scan elements per block

// ---------------- scratch (device globals; no allocation allowed) ----------
__device__ __align__(256) float g_deg[NN];      // out-degree (by row)
__device__ __align__(256) int   g_cnt[NN];      // in-degree (by col)
__device__ __align__(256) float g_dis[NN];      // deg^-1/2
__device__ __align__(256) int   g_ptr[NN + 1];  // CSR row pointers (by dst)
__device__ __align__(256) int   g_fill[NN];     // atomic cursors
__device__ __align__(256) int   g_bsum[256];    // scan block sums
__device__ __align__(256) int   g_redge[EE];    // src row per CSR slot (4B)
__device__ __align__(256) float g_T1[NN * DD];
__device__ __align__(256) float g_P[NN * DD];
__device__ __align__(256) float g_acc[NN * DD];
__device__ __align__(256) float g_colsum[DD];
__device__ __align__(256) float g_colsumsq[DD];
__device__ unsigned g_bar[4];                   // grid barrier counters
__device__ unsigned g_exit;                     // exit counter (resets bars)

// ---------------- packed f32x2 FMA (SASS FFMA2) -----------------------------
__device__ __forceinline__ void ffma2(unsigned long long& d,
                                      unsigned long long a,
                                      unsigned long long b) {
    asm("fma.rn.f32x2 %0, %1, %2, %0;" : "+l"(d) : "l"(a), "l"(b));
}

// ---------------- software grid barrier (148 co-resident blocks) ------------
__device__ __forceinline__ void grid_barrier(int i) {
    __syncthreads();
    if (threadIdx.x == 0) {
        __threadfence();
        atomicAdd(&g_bar[i], 1u);
        while (atomicAdd(&g_bar[i], 0u) < NGB) {}
    }
    __syncthreads();
    __threadfence();
}

// ---------------- fused preprocessing: hist -> scan -> scatter --------------
__global__ __launch_bounds__(256, 1)
void prep_kernel(const int* __restrict__ ei) {
    int tid = threadIdx.x;
    int bid = blockIdx.x;
    int gid = bid * 256 + tid;

    // ---- Phase A: histogram (deg/cnt zeroed by prev replay's spmm pass 0) --
    if (bid == 0 && tid < DD) { g_colsum[tid] = 0.f; g_colsumsq[tid] = 0.f; }
    for (int e = gid; e < EE; e += NGB * 256) {
        int r = ei[e], c = ei[EE + e];
        if (r != c) {
            atomicAdd(&g_deg[r], 1.0f);   // no return use -> REDG
            atomicAdd(&g_cnt[c], 1);
        }
    }
    grid_barrier(0);

    // ---- Phase B1: local scan of 512-elem chunk + block sum ----------------
    __shared__ int sh[256];
    __shared__ int s_off;
    int base = bid * SCHUNK;
    int i0 = base + 2 * tid, i1 = i0 + 1;
    int c0 = (i0 < NN) ? g_cnt[i0] : 0;
    int c1 = (i1 < NN) ? g_cnt[i1] : 0;
    int s = c0 + c1;
    sh[tid] = s;
    __syncthreads();
#pragma unroll
    for (int off = 1; off < 256; off <<= 1) {
        int t = (tid >= off) ? sh[tid - off] : 0;
        __syncthreads();
        sh[tid] += t;
        __syncthreads();
    }
    int excl = sh[tid] - s;              // block-local exclusive prefix
    if (tid == 255) g_bsum[bid] = sh[255];
    grid_barrier(1);

    // ---- Phase B2: redundant scan of 148 block sums, apply, dis ------------
    {
        __shared__ int sh2[256];
        int v = (tid < NGB) ? g_bsum[tid] : 0;
        sh2[tid] = v;
        __syncthreads();
#pragma unroll
        for (int off = 1; off < 256; off <<= 1) {
            int t = (tid >= off) ? sh2[tid - off] : 0;
            __syncthreads();
            sh2[tid] += t;
            __syncthreads();
        }
        if (tid == bid) s_off = sh2[tid] - v;          // exclusive offset
        if (bid == 0 && tid == NGB - 1) g_ptr[NN] = sh2[NGB - 1];
        __syncthreads();
    }
    int off = s_off;
    if (i0 < NN) {
        int p = excl + off;
        g_ptr[i0] = p; g_fill[i0] = p;
        float d = g_deg[i0];
        g_dis[i0] = (d > 0.f) ? rsqrtf(fmaxf(d, 1e-12f)) : 0.f;
    }
    if (i1 < NN) {
        int p = excl + c0 + off;
        g_ptr[i1] = p; g_fill[i1] = p;
        float d = g_deg[i1];
        g_dis[i1] = (d > 0.f) ? rsqrtf(fmaxf(d, 1e-12f)) : 0.f;
    }
    grid_barrier(2);

    // ---- Phase C: scatter src rows (4B records), x4-batched chains ---------
    for (int e4 = gid * 4; e4 < EE; e4 += NGB * 256 * 4) {
        int4 rr = *reinterpret_cast<const int4*>(ei + e4);
        int4 cc = *reinterpret_cast<const int4*>(ei + EE + e4);
        int r[4] = {rr.x, rr.y, rr.z, rr.w};
        int c[4] = {cc.x, cc.y, cc.z, cc.w};
#pragma unroll
        for (int i = 0; i < 4; i++) {
            if (r[i] == c[i]) continue;
            int pos = atomicAdd(&g_fill[c[i]], 1);
            g_redge[pos] = r[i];
        }
    }

    // ---- exit: last block resets barrier counters for next replay ----------
    if (tid == 0) {
        __threadfence();
        unsigned v = atomicAdd(&g_exit, 1u);
        if (v == NGB - 1) {
            g_bar[0] = 0; g_bar[1] = 0; g_bar[2] = 0; g_bar[3] = 0;
            g_exit = 0;
        }
    }
}

// ---------------- pull-mode SpMM with on-the-fly norm -----------------------
// One warp per destination node; lane covers features {lane, +32, +64}.
// norm = -dis[r] * dis[node]; dis[node] hoisted, dis[r] broadcast load.
__global__ void spmm_pull_kernel(int pass, const float* __restrict__ x) {
    if (pass == 0) {                     // zero deg/cnt for NEXT replay
        int zi = blockIdx.x * 256 + threadIdx.x;
        if (zi < NN) { g_deg[zi] = 0.f; g_cnt[zi] = 0; }
    }

    const float* src = (pass == 0) ? x : g_T1;
    float* dst = (pass == 0) ? g_T1 : g_P;

    int node = (blockIdx.x * blockDim.x + threadIdx.x) >> 5;
    if (node >= NN) return;
    int lane = threadIdx.x & 31;

    float dn = -g_dis[node];             // fold the minus sign here
    int beg = g_ptr[node], end = g_ptr[node + 1];
    float a0 = 0.f, a1 = 0.f, a2 = 0.f;

    int e = beg;
    for (; e + 1 < end; e += 2) {
        int r0 = __ldg(&g_redge[e]);
        int r1 = __ldg(&g_redge[e + 1]);
        float n0 = __ldg(&g_dis[r0]) * dn;
        float n1 = __ldg(&g_dis[r1]) * dn;
        const float* s0 = src + r0 * DD;
        const float* s1 = src + r1 * DD;
        float v00 = __ldg(s0 + lane), v01 = __ldg(s0 + lane + 32), v02 = __ldg(s0 + lane + 64);
        float v10 = __ldg(s1 + lane), v11 = __ldg(s1 + lane + 32), v12 = __ldg(s1 + lane + 64);
        a0 += n0 * v00 + n1 * v10;
        a1 += n0 * v01 + n1 * v11;
        a2 += n0 * v02 + n1 * v12;
    }
    if (e < end) {
        int r0 = __ldg(&g_redge[e]);
        float n0 = __ldg(&g_dis[r0]) * dn;
        const float* s0 = src + r0 * DD;
        a0 += n0 * __ldg(s0 + lane);
        a1 += n0 * __ldg(s0 + lane + 32);
        a2 += n0 * __ldg(s0 + lane + 64);
    }

    float* d = dst + node * DD;
    d[lane] = a0;
    d[lane + 32] = a1;
    d[lane + 64] = a2;
}

// ---------------- persistent GEMM (round-16 verbatim) -----------------------
#define GEMM_THREADS 384
#define RPB 64
#define NSM 148
#define WS_STRIDE 100
#define RS 100
#define RS4 25
#define WS_MAT (DD * WS_STRIDE)
#define GBLK ((NN + RPB - 1) / RPB)
#define ROW4 (DD / 4)
#define TILE4 (RPB * ROW4)
#define PFQ (TILE4 / GEMM_THREADS)
#define SMEM_FLOATS (3 * WS_MAT + DD + 3 * RPB * RS + 2 * DD)
#define SMEM_BYTES (SMEM_FLOATS * 4)

__global__ __launch_bounds__(GEMM_THREADS, 1)
void gemm_kernel(const float* __restrict__ x, const float* __restrict__ W,
                 const float* __restrict__ bias) {
    extern __shared__ float smem[];
    float* Ws   = smem;
    float* bs   = Ws + 3 * WS_MAT;
    float* xs   = bs + DD;
    float* t1s  = xs + RPB * RS;
    float* t2s  = t1s + RPB * RS;
    float* stat = t2s + RPB * RS;

    int tid = threadIdx.x;
    int wid = tid >> 5, lane = tid & 31;
    int tx = (wid % 3) * 8 + (lane & 7);
    int ty = (wid / 3) * 4 + (lane >> 3);

    for (int i = tid; i < 3 * DD * DD; i += GEMM_THREADS) {
        int kk = i / (DD * DD);
        int rem = i - kk * DD * DD;
        int k = rem / DD;
        int j = rem - k * DD;
        Ws[kk * WS_MAT + j * WS_STRIDE + k] = W[i];
    }
    if (tid < DD) bs[tid] = bias[tid];
    if (tid < 2 * DD) stat[tid] = 0.f;

    const float4* x4  = reinterpret_cast<const float4*>(x);
    const float4* t14 = reinterpret_cast<const float4*>(g_T1);
    const float4* p4  = reinterpret_cast<const float4*>(g_P);
    float4* xs4  = reinterpret_cast<float4*>(xs);
    float4* t1s4 = reinterpret_cast<float4*>(t1s);
    float4* t2s4 = reinterpret_cast<float4*>(t2s);

    float4 pf[3 * PFQ];
    int tile = blockIdx.x;
    {
#pragma unroll
        for (int q = 0; q < PFQ; q++) {
            int idx = tid + q * GEMM_THREADS;
            int row = tile * RPB + idx / ROW4;
            float4 xv = make_float4(0.f, 0.f, 0.f, 0.f), t1v = xv, t2v = xv;
            if (row < NN) {
                int gi = row * ROW4 + (idx % ROW4);
                xv = __ldg(x4 + gi);
                t1v = t14[gi];
                float4 pv = p4[gi];
                t2v = make_float4(2.f * pv.x - xv.x, 2.f * pv.y - xv.y,
                                  2.f * pv.z - xv.z, 2.f * pv.w - xv.w);
            }
            pf[q * 3 + 0] = xv; pf[q * 3 + 1] = t1v; pf[q * 3 + 2] = t2v;
        }
    }
    __syncthreads();
#pragma unroll
    for (int q = 0; q < PFQ; q++) {
        int idx = tid + q * GEMM_THREADS;
        int si = (idx / ROW4) * RS4 + (idx % ROW4);
        xs4[si] = pf[q * 3 + 0]; t1s4[si] = pf[q * 3 + 1]; t2s4[si] = pf[q * 3 + 2];
    }
    __syncthreads();

    float cs[4] = {0.f, 0.f, 0.f, 0.f};
    float cs2[4] = {0.f, 0.f, 0.f, 0.f};

    for (;;) {
        int next = tile + NSM;
        bool has_next = (next < GBLK);

        if (has_next) {
#pragma unroll
            for (int q = 0; q < PFQ; q++) {
                int idx = tid + q * GEMM_THREADS;
                int row = next * RPB + idx / ROW4;
                float4 xv = make_float4(0.f, 0.f, 0.f, 0.f), t1v = xv, t2v = xv;
                if (row < NN) {
                    int gi = row * ROW4 + (idx % ROW4);
                    xv = __ldg(x4 + gi);
                    t1v = t14[gi];
                    float4 pv = p4[gi];
                    t2v = make_float4(2.f * pv.x - xv.x, 2.f * pv.y - xv.y,
                                      2.f * pv.z - xv.z, 2.f * pv.w - xv.w);
                }
                pf[q * 3 + 0] = xv; pf[q * 3 + 1] = t1v; pf[q * 3 + 2] = t2v;
            }
        }

        unsigned long long acc[4][4];
#pragma unroll
        for (int r = 0; r < 4; r++)
#pragma unroll
            for (int jj = 0; jj < 4; jj++) acc[r][jj] = 0ULL;

        for (int k = 0; k < DD; k += 4) {
            ulonglong2 w0[4], w1[4], w2[4];
#pragma unroll
            for (int jj = 0; jj < 4; jj++) {
                int j = tx + jj * 24;
                w0[jj] = *reinterpret_cast<const ulonglong2*>(&Ws[0 * WS_MAT + j * WS_STRIDE + k]);
                w1[jj] = *reinterpret_cast<const ulonglong2*>(&Ws[1 * WS_MAT + j * WS_STRIDE + k]);
                w2[jj] = *reinterpret_cast<const ulonglong2*>(&Ws[2 * WS_MAT + j * WS_STRIDE + k]);
            }
#pragma unroll
            for (int r = 0; r < 4; r++) {
                int rofs = (ty + 16 * r) * RS + k;
                ulonglong2 xv = *reinterpret_cast<const ulonglong2*>(&xs[rofs]);
                ulonglong2 av = *reinterpret_cast<const ulonglong2*>(&t1s[rofs]);
                ulonglong2 bv = *reinterpret_cast<const ulonglong2*>(&t2s[rofs]);
#pragma unroll
                for (int jj = 0; jj < 4; jj++) {
                    ffma2(acc[r][jj], xv.x, w0[jj].x);
                    ffma2(acc[r][jj], xv.y, w0[jj].y);
                    ffma2(acc[r][jj], av.x, w1[jj].x);
                    ffma2(acc[r][jj], av.y, w1[jj].y);
                    ffma2(acc[r][jj], bv.x, w2[jj].x);
                    ffma2(acc[r][jj], bv.y, w2[jj].y);
                }
            }
        }

        int base = tile * RPB;
#pragma unroll
        for (int jj = 0; jj < 4; jj++) {
            int j = tx + jj * 24;
            float bj = bs[j];
#pragma unroll
            for (int r = 0; r < 4; r++) {
                int row = base + ty + 16 * r;
                if (row < NN) {
                    unsigned int lo_b, hi_b;
                    asm("mov.b64 {%0, %1}, %2;" : "=r"(lo_b), "=r"(hi_b) : "l"(acc[r][jj]));
                    float v = __uint_as_float(lo_b) + __uint_as_float(hi_b) + bj;
                    g_acc[row * DD + j] = v;
                    cs[jj] += v; cs2[jj] += v * v;
                }
            }
        }

        if (!has_next) break;
        __syncthreads();
#pragma unroll
        for (int q = 0; q < PFQ; q++) {
            int idx = tid + q * GEMM_THREADS;
            int si = (idx / ROW4) * RS4 + (idx % ROW4);
            xs4[si] = pf[q * 3 + 0]; t1s4[si] = pf[q * 3 + 1]; t2s4[si] = pf[q * 3 + 2];
        }
        __syncthreads();
        tile = next;
    }

    __syncthreads();
#pragma unroll
    for (int jj = 0; jj < 4; jj++) {
        int j = tx + jj * 24;
        atomicAdd(&stat[j], cs[jj]);
        atomicAdd(&stat[DD + j], cs2[jj]);
    }
    __syncthreads();
    if (tid < DD) {
        atomicAdd(&g_colsum[tid], stat[tid]);
        atomicAdd(&g_colsumsq[tid], stat[DD + tid]);
    }
}

// ---------------- BatchNorm: stats finalize fused into apply ----------------
__global__ void bn_apply_kernel(const float* __restrict__ gamma,
                                const float* __restrict__ beta,
                                float* __restrict__ out) {
    __shared__ float sc[DD], sh[DD];
    if (threadIdx.x < DD) {
        int j = threadIdx.x;
        float inv_n = 1.0f / (float)NN;
        float mean = g_colsum[j] * inv_n;
        float var = fmaxf(g_colsumsq[j] * inv_n - mean * mean, 0.f);
        float istd = rsqrtf(var + 1e-5f);
        float s = gamma[j] * istd;
        sc[j] = s;
        sh[j] = beta[j] - mean * s;
    }
    __syncthreads();
    int tid = blockIdx.x * blockDim.x + threadIdx.x;
    int stride = gridDim.x * blockDim.x;
    const float4* in4 = reinterpret_cast<const float4*>(g_acc);
    float4* o4 = reinterpret_cast<float4*>(out);
    for (int i = tid; i < NV4; i += stride) {
        int c4 = i % (DD / 4);
        int j = c4 * 4;
        float4 v = in4[i];
        o4[i] = make_float4(v.x * sc[j]     + sh[j],
                            v.y * sc[j + 1] + sh[j + 1],
                            v.z * sc[j + 2] + sh[j + 2],
                            v.w * sc[j + 3] + sh[j + 3]);
    }
}

// ---------------- launch ----------------------------------------------------
extern "C" void kernel_launch(void* const* d_in, const int* in_sizes, int n_in,
                              void* d_out, int out_size) {
    const float* x     = (const float*)d_in[0];
    const int*   ei    = (const int*)d_in[1];
    const float* W     = (const float*)d_in[2];
    const float* bias  = (const float*)d_in[3];
    const float* gamma = (const float*)d_in[4];
    const float* beta  = (const float*)d_in[5];
    float* out = (float*)d_out;

    cudaFuncSetAttribute(gemm_kernel,
                         cudaFuncAttributeMaxDynamicSharedMemorySize, SMEM_BYTES);

    // fused hist -> scan -> scatter (one persistent launch)
    prep_kernel<<<NGB, 256>>>(ei);
    // prop 1: T1 = L_hat @ x  (+ deg/cnt zero for next replay)
    spmm_pull_kernel<<<(NN * 32 + 255) / 256, 256>>>(0, x);
    // prop 2: P = L_hat @ T1
    spmm_pull_kernel<<<(NN * 32 + 255) / 256, 256>>>(1, x);
    gemm_kernel<<<NSM, GEMM_THREADS, SMEM_BYTES>>>(x, W, bias);
    bn_apply_kernel<<<2048, 256>>>(gamma, beta, out);
}